// round 11
// baseline (speedup 1.0000x reference)
#include <cuda_runtime.h>
#include <cuda_bf16.h>
#include <cuda_fp16.h>
#include <cstdint>

#define IN_DIM   32
#define NB       11
#define FPAD     10                    // basis cols per feature in GEMM (sin/cos only)
#define HID      64
#define TILE_M   128
#define NCHUNK   4
#define FPC      8                     // features per chunk
#define KSTEPS   5                     // k16-steps per chunk (80 cols)
#define KS_TOTAL 20
#define THREADS  256
#define NCTAS    296                   // 148 SMs x 2 resident CTAs

#define A_STRIDE_B  176                // bytes per A row (88 halves; 80 used)

// ---- SMEM layout (bytes): double-buffered A (fp16) + resident B ----
#define ABUF_BYTES  (TILE_M * A_STRIDE_B)       // 22528
#define B_OFF       (2 * ABUF_BYTES)            // 45056
#define BFRAG_BYTES (KS_TOTAL * 2 * 32 * 32)    // 40960  [ksg][nw][lane][j*8B]
#define SMEM_TOTAL  (B_OFF + BFRAG_BYTES)       // 86016

__device__ __align__(16) unsigned char g_Bh[BFRAG_BYTES];   // fp16 fragments (packed)
__device__ float g_c0[HID];            // sum_f (W[f][0][:] + b[f][:]), fp32 exact

// ---------------------------------------------------------------- helpers
__device__ __forceinline__ uint32_t smem_u32(const void* p) {
    uint32_t a;
    asm("{ .reg .u64 t; cvta.to.shared.u64 t, %1; cvt.u32.u64 %0, t; }"
        : "=r"(a) : "l"(p));
    return a;
}
__device__ __forceinline__ void ldm4(uint32_t* r, uint32_t a) {
    asm volatile("ldmatrix.sync.aligned.m8n8.x4.shared.b16 {%0,%1,%2,%3}, [%4];"
                 : "=r"(r[0]), "=r"(r[1]), "=r"(r[2]), "=r"(r[3]) : "r"(a));
}
__device__ __forceinline__ void sts64(uint32_t a, uint32_t v0, uint32_t v1) {
    asm volatile("st.shared.v2.b32 [%0], {%1, %2};" :: "r"(a), "r"(v0), "r"(v1) : "memory");
}
__device__ __forceinline__ void lds128(uint32_t* r, uint32_t a) {
    asm volatile("ld.shared.v4.b32 {%0,%1,%2,%3}, [%4];"
                 : "=r"(r[0]), "=r"(r[1]), "=r"(r[2]), "=r"(r[3]) : "r"(a));
}
__device__ __forceinline__ void mma16816(float* d, const uint32_t* a, const uint32_t* b) {
    asm volatile(
        "mma.sync.aligned.m16n8k16.row.col.f32.f16.f16.f32 "
        "{%0,%1,%2,%3}, {%4,%5,%6,%7}, {%8,%9}, {%0,%1,%2,%3};"
        : "+f"(d[0]), "+f"(d[1]), "+f"(d[2]), "+f"(d[3])
        : "r"(a[0]), "r"(a[1]), "r"(a[2]), "r"(a[3]), "r"(b[0]), "r"(b[1]));
}

// sin/cos harmonics 1..5 of xv -> v[10] = {s1,c1,s2,c2,...,s5,c5}
__device__ __forceinline__ void sincos_harm(float xv, float* v) {
    float t  = fmaf(xv, 0.3183098861837907f, 12582912.0f);
    uint32_t ti = __float_as_uint(t);
    float nf = t - 12582912.0f;
    float rr = fmaf(nf, -3.14159274101257324f, xv);
    rr = fmaf(nf, 8.74227800037247e-8f, rr);
    float sgn = (ti & 1u) ? -1.0f : 1.0f;

    float r2 = rr * rr;
    float sp = -2.50521083854e-8f;
    sp = fmaf(sp, r2, 2.75573192240e-6f);
    sp = fmaf(sp, r2, -1.98412698413e-4f);
    sp = fmaf(sp, r2, 8.33333333333e-3f);
    sp = fmaf(sp, r2, -1.66666666667e-1f);
    float s1 = fmaf(sp * r2, rr, rr);
    float cp = 2.08767569879e-9f;
    cp = fmaf(cp, r2, -2.75573192240e-7f);
    cp = fmaf(cp, r2, 2.48015873016e-5f);
    cp = fmaf(cp, r2, -1.38888888889e-3f);
    cp = fmaf(cp, r2, 4.16666666667e-2f);
    cp = fmaf(cp, r2, -0.5f);
    float c1 = fmaf(cp, r2, 1.0f);
    s1 *= sgn; c1 *= sgn;

    float s2 = 2.f * s1 * c1;
    float c2 = fmaf(c1, c1, -(s1 * s1));
    float s3 = s2 * c1 + c2 * s1;
    float c3 = c2 * c1 - s2 * s1;
    float s4 = s3 * c1 + c3 * s1;
    float c4 = c3 * c1 - s3 * s1;
    float s5 = s4 * c1 + c4 * s1;
    float c5 = c4 * c1 - s4 * s1;
    v[0] = s1; v[1] = c1; v[2] = s2; v[3] = c2; v[4] = s3;
    v[5] = c3; v[6] = s4; v[7] = c4; v[8] = s5; v[9] = c5;
}

// ---------------------------------------------------------------- prep kernel
// B[k][n], k = f*10 + c (c -> basis col c+1) as fp16 in PACKED fragment layout:
// offset = ((ksg*2 + nw)*32 + lane)*32 + j*8, so a consumer warp's 4 fragments
// for one k-step are 32 contiguous bytes per lane (2x LDS.128).
__global__ void prep_kernel(const float* __restrict__ W, const float* __restrict__ bias) {
    int idx = blockIdx.x * blockDim.x + threadIdx.x;   // (ksg, nt, t)
    if (idx < HID) {
        float s = 0.f;
        #pragma unroll
        for (int f = 0; f < IN_DIM; f++)
            s += W[(f * NB) * HID + idx] + bias[f * HID + idx];
        g_c0[idx] = s;
    }
    if (idx >= KS_TOTAL * 8 * 32) return;
    int t   = idx & 31;
    int nt  = (idx >> 5) & 7;
    int ksg = idx >> 8;
    int n     = nt * 8 + (t >> 2);
    int kbase = ksg * 16 + (t & 3) * 2;

    uint32_t hi[2];
    #pragma unroll
    for (int half = 0; half < 2; half++) {
        int k0 = kbase + half * 8;
        float v0 = W[((k0 / FPAD) * NB + (k0 % FPAD) + 1) * HID + n];
        int k1 = k0 + 1;
        float v1 = W[((k1 / FPAD) * NB + (k1 % FPAD) + 1) * HID + n];
        __half2 h2 = __floats2half2_rn(v0, v1);
        hi[half] = *(uint32_t*)&h2;
    }
    int off = ((ksg * 2 + (nt >> 2)) * 32 + t) * 32 + (nt & 3) * 8;
    *(uint2*)(g_Bh + off) = make_uint2(hi[0], hi[1]);
}

// ---------------------------------------------------------------- A generation
// 512 jobs: 128 rows x 4 feature-pairs; each job does 2 sincos + 5 STS.64
__device__ __forceinline__ void gen_chunk(const float* __restrict__ x,
                                          uint32_t sbase, long row0, int n_rows,
                                          int ch, int buf, int tid)
{
    const uint32_t hoff = sbase + buf * ABUF_BYTES;
    #pragma unroll
    for (int i = 0; i < 2; i++) {
        const int job = tid + THREADS * i;     // 0..511
        const int r   = job >> 2;
        const int fp  = job & 3;
        const long grow = row0 + r;
        const int f0 = ch * FPC + fp * 2;

        float2 xv2 = make_float2(0.f, 0.f);
        if (grow < n_rows)
            xv2 = __ldg((const float2*)(x + grow * IN_DIM + f0));

        float v[20];
        sincos_harm(xv2.x, v);
        sincos_harm(xv2.y, v + 10);

        const uint32_t wb = hoff + r * A_STRIDE_B + fp * 40;
        #pragma unroll
        for (int p = 0; p < 5; p++) {
            __half2 a = __floats2half2_rn(v[4 * p + 0], v[4 * p + 1]);
            __half2 b = __floats2half2_rn(v[4 * p + 2], v[4 * p + 3]);
            sts64(wb + p * 8, *(uint32_t*)&a, *(uint32_t*)&b);
        }
    }
}

// ---------------------------------------------------------------- main kernel
__global__ void __launch_bounds__(THREADS, 2)
kan_mma_kernel(const float* __restrict__ x, float* __restrict__ out,
               int n_rows, int ntiles)
{
    extern __shared__ __align__(16) unsigned char smem[];
    const uint32_t sbase = smem_u32(smem);
    const int tid  = threadIdx.x;
    const int lane = tid & 31;
    const int wid  = tid >> 5;
    const int mw   = wid & 3;    // M warp: rows mw*32
    const int nw   = wid >> 2;   // N warp: cols nw*32

    const int lrow = lane & 15, lcol = lane >> 4;
    const uint32_t aOff = (uint32_t)(mw * 32 + lrow) * A_STRIDE_B + lcol * 16;
    const uint32_t bLane = sbase + B_OFF + (uint32_t)(nw * 32 + lane) * 32;

    // ---- stage B into SMEM once per (persistent) CTA ----
    {
        const uint4* src = (const uint4*)g_Bh;
        uint4* dst = (uint4*)(smem + B_OFF);
        #pragma unroll
        for (int i = tid; i < BFRAG_BYTES / 16; i += THREADS)
            dst[i] = src[i];
    }

    // epilogue constant (ones-col + bias), fp32 exact
    float c0v[4][2];
    #pragma unroll
    for (int j = 0; j < 4; j++) {
        const int col = nw * 32 + j * 8 + (lane & 3) * 2;
        c0v[j][0] = __ldg(&g_c0[col]);
        c0v[j][1] = __ldg(&g_c0[col + 1]);
    }

    int buf = 0;
    if (blockIdx.x < (unsigned)ntiles)
        gen_chunk(x, sbase, (long)blockIdx.x * TILE_M, n_rows, 0, 0, tid);
    __syncthreads();

    for (int tile = blockIdx.x; tile < ntiles; tile += gridDim.x) {
        const long tile_row0 = (long)tile * TILE_M;

        float d[2][4][4];
        #pragma unroll
        for (int mt = 0; mt < 2; mt++)
            #pragma unroll
            for (int j = 0; j < 4; j++)
                #pragma unroll
                for (int e = 0; e < 4; e++) d[mt][j][e] = 0.f;

        for (int ch = 0; ch < NCHUNK; ch++) {
            // produce next chunk (next tile's chunk 0 when wrapping)
            const int  ntile = (ch < NCHUNK - 1) ? tile : tile + gridDim.x;
            const int  nch   = (ch < NCHUNK - 1) ? ch + 1 : 0;
            if (ntile < ntiles)
                gen_chunk(x, sbase, (long)ntile * TILE_M, n_rows, nch, buf ^ 1, tid);

            // === mma on current buffer: 5 k-steps x (2 mt x 4 nt) ===
            const uint32_t aBase = sbase + buf * ABUF_BYTES + aOff;
            #pragma unroll
            for (int s = 0; s < KSTEPS; s++) {
                uint32_t aAddr = aBase + s * 32;
                uint32_t ah[2][4];
                ldm4(ah[0], aAddr);
                ldm4(ah[1], aAddr + 16 * A_STRIDE_B);

                // B: 4 fragments = 32 contiguous bytes/lane -> 2x LDS.128
                const int ksg = ch * KSTEPS + s;
                uint32_t bh[8];
                lds128(bh,     bLane + (uint32_t)ksg * 2048);
                lds128(bh + 4, bLane + (uint32_t)ksg * 2048 + 16);

                #pragma unroll
                for (int mt = 0; mt < 2; mt++)
                    #pragma unroll
                    for (int j = 0; j < 4; j++)
                        mma16816(d[mt][j], ah[mt], bh + 2 * j);
            }
            __syncthreads();
            buf ^= 1;
        }

        // ---- epilogue: add fp32 constant, store ----
        #pragma unroll
        for (int mt = 0; mt < 2; mt++) {
            #pragma unroll
            for (int half = 0; half < 2; half++) {
                const long grow = tile_row0 + mw * 32 + mt * 16 + (lane >> 2) + half * 8;
                if (grow < n_rows) {
                    #pragma unroll
                    for (int j = 0; j < 4; j++) {
                        const int col = nw * 32 + j * 8 + (lane & 3) * 2;
                        float2 v;
                        v.x = d[mt][j][half * 2 + 0] + c0v[j][0];
                        v.y = d[mt][j][half * 2 + 1] + c0v[j][1];
                        *(float2*)(out + grow * HID + col) = v;
                    }
                }
            }
        }
    }
}

// ---------------------------------------------------------------- launch
extern "C" void kernel_launch(void* const* d_in, const int* in_sizes, int n_in,
                              void* d_out, int out_size)
{
    const float* x = (const float*)d_in[0];
    const float* W = (const float*)d_in[1];
    const float* b = (const float*)d_in[2];
    float* out = (float*)d_out;

    const int n_rows = in_sizes[0] / IN_DIM;    // 131072
    const int ntiles = (n_rows + TILE_M - 1) / TILE_M;
    const int grid = ntiles < NCTAS ? ntiles : NCTAS;

    cudaFuncSetAttribute(kan_mma_kernel,
                         cudaFuncAttributeMaxDynamicSharedMemorySize, SMEM_TOTAL);

    prep_kernel<<<(KS_TOTAL * 8 * 32 + 255) / 256, 256>>>(W, b);
    kan_mma_kernel<<<grid, THREADS, SMEM_TOTAL>>>(x, out, n_rows, ntiles);
}

// round 12
// speedup vs baseline: 1.0674x; 1.0674x over previous
#include <cuda_runtime.h>
#include <cuda_bf16.h>
#include <cuda_fp16.h>
#include <cstdint>

#define IN_DIM   32
#define NB       11
#define FPAD     10                    // basis cols per feature in GEMM (sin/cos only)
#define HID      64
#define TILE_M   128
#define NCHUNK   4
#define FPC      8                     // features per chunk
#define KSTEPS   5                     // k16-steps per chunk (80 cols)
#define KS_TOTAL 20
#define THREADS  256
#define OCC      3
#define NCTAS    (148 * OCC)           // persistent grid

#define A_STRIDE_B  176                // bytes per A row (88 halves; 80 used)

// ---- SMEM layout (bytes): double-buffered A (fp16) ----
#define ABUF_BYTES  (TILE_M * A_STRIDE_B)       // 22528
#define SMEM_TOTAL  (2 * ABUF_BYTES)            // 45056  (x3 CTAs = 135K/SM)

#define BFRAG_BYTES (KS_TOTAL * 8 * 32 * 8)     // 40960

__device__ __align__(16) unsigned char g_Bh[BFRAG_BYTES];   // fp16 fragments
__device__ float g_c0[HID];            // sum_f (W[f][0][:] + b[f][:]), fp32 exact

// ---------------------------------------------------------------- helpers
__device__ __forceinline__ uint32_t smem_u32(const void* p) {
    uint32_t a;
    asm("{ .reg .u64 t; cvta.to.shared.u64 t, %1; cvt.u32.u64 %0, t; }"
        : "=r"(a) : "l"(p));
    return a;
}
__device__ __forceinline__ void ldm4(uint32_t* r, uint32_t a) {
    asm volatile("ldmatrix.sync.aligned.m8n8.x4.shared.b16 {%0,%1,%2,%3}, [%4];"
                 : "=r"(r[0]), "=r"(r[1]), "=r"(r[2]), "=r"(r[3]) : "r"(a));
}
__device__ __forceinline__ void sts64(uint32_t a, uint32_t v0, uint32_t v1) {
    asm volatile("st.shared.v2.b32 [%0], {%1, %2};" :: "r"(a), "r"(v0), "r"(v1) : "memory");
}
__device__ __forceinline__ void mma16816(float* d, const uint32_t* a, const uint32_t* b) {
    asm volatile(
        "mma.sync.aligned.m16n8k16.row.col.f32.f16.f16.f32 "
        "{%0,%1,%2,%3}, {%4,%5,%6,%7}, {%8,%9}, {%0,%1,%2,%3};"
        : "+f"(d[0]), "+f"(d[1]), "+f"(d[2]), "+f"(d[3])
        : "r"(a[0]), "r"(a[1]), "r"(a[2]), "r"(a[3]), "r"(b[0]), "r"(b[1]));
}

// sin/cos harmonics 1..5 of xv -> v[10] = {s1,c1,s2,c2,...,s5,c5}
__device__ __forceinline__ void sincos_harm(float xv, float* v) {
    float t  = fmaf(xv, 0.3183098861837907f, 12582912.0f);
    uint32_t ti = __float_as_uint(t);
    float nf = t - 12582912.0f;
    float rr = fmaf(nf, -3.14159274101257324f, xv);
    rr = fmaf(nf, 8.74227800037247e-8f, rr);
    float sgn = (ti & 1u) ? -1.0f : 1.0f;

    float r2 = rr * rr;
    float sp = -2.50521083854e-8f;
    sp = fmaf(sp, r2, 2.75573192240e-6f);
    sp = fmaf(sp, r2, -1.98412698413e-4f);
    sp = fmaf(sp, r2, 8.33333333333e-3f);
    sp = fmaf(sp, r2, -1.66666666667e-1f);
    float s1 = fmaf(sp * r2, rr, rr);
    float cp = 2.08767569879e-9f;
    cp = fmaf(cp, r2, -2.75573192240e-7f);
    cp = fmaf(cp, r2, 2.48015873016e-5f);
    cp = fmaf(cp, r2, -1.38888888889e-3f);
    cp = fmaf(cp, r2, 4.16666666667e-2f);
    cp = fmaf(cp, r2, -0.5f);
    float c1 = fmaf(cp, r2, 1.0f);
    s1 *= sgn; c1 *= sgn;

    float s2 = 2.f * s1 * c1;
    float c2 = fmaf(c1, c1, -(s1 * s1));
    float s3 = s2 * c1 + c2 * s1;
    float c3 = c2 * c1 - s2 * s1;
    float s4 = s3 * c1 + c3 * s1;
    float c4 = c3 * c1 - s3 * s1;
    float s5 = s4 * c1 + c4 * s1;
    float c5 = c4 * c1 - s4 * s1;
    v[0] = s1; v[1] = c1; v[2] = s2; v[3] = c2; v[4] = s3;
    v[5] = c3; v[6] = s4; v[7] = c4; v[8] = s5; v[9] = c5;
}

// ---------------------------------------------------------------- prep kernel
// B[k][n], k = f*10 + c (c -> basis col c+1) as fp16 in mma B-fragment layout.
// Also g_c0 = sum_f(W[f][0]+b[f]).
__global__ void prep_kernel(const float* __restrict__ W, const float* __restrict__ bias) {
    int idx = blockIdx.x * blockDim.x + threadIdx.x;
    if (idx < HID) {
        float s = 0.f;
        #pragma unroll
        for (int f = 0; f < IN_DIM; f++)
            s += W[(f * NB) * HID + idx] + bias[f * HID + idx];
        g_c0[idx] = s;
    }
    if (idx >= KS_TOTAL * 8 * 32) return;
    int t   = idx & 31;
    int nt  = (idx >> 5) & 7;
    int ksg = idx >> 8;
    int n     = nt * 8 + (t >> 2);
    int kbase = ksg * 16 + (t & 3) * 2;

    uint32_t hi[2];
    #pragma unroll
    for (int half = 0; half < 2; half++) {
        int k0 = kbase + half * 8;
        float v0 = W[((k0 / FPAD) * NB + (k0 % FPAD) + 1) * HID + n];
        int k1 = k0 + 1;
        float v1 = W[((k1 / FPAD) * NB + (k1 % FPAD) + 1) * HID + n];
        __half2 h2 = __floats2half2_rn(v0, v1);
        hi[half] = *(uint32_t*)&h2;
    }
    *(uint2*)(g_Bh + idx * 8) = make_uint2(hi[0], hi[1]);
}

// ---------------------------------------------------------------- A generation
// 512 jobs: 128 rows x 4 feature-pairs; each job does 2 sincos + 5 STS.64
__device__ __forceinline__ void gen_chunk(const float* __restrict__ x,
                                          uint32_t sbase, long row0, int n_rows,
                                          int ch, int buf, int tid)
{
    const uint32_t hoff = sbase + buf * ABUF_BYTES;
    #pragma unroll
    for (int i = 0; i < 2; i++) {
        const int job = tid + THREADS * i;     // 0..511
        const int r   = job >> 2;
        const int fp  = job & 3;
        const long grow = row0 + r;
        const int f0 = ch * FPC + fp * 2;

        float2 xv2 = make_float2(0.f, 0.f);
        if (grow < n_rows)
            xv2 = __ldg((const float2*)(x + grow * IN_DIM + f0));

        float v[20];
        sincos_harm(xv2.x, v);
        sincos_harm(xv2.y, v + 10);

        const uint32_t wb = hoff + r * A_STRIDE_B + fp * 40;
        #pragma unroll
        for (int p = 0; p < 5; p++) {
            __half2 a = __floats2half2_rn(v[4 * p + 0], v[4 * p + 1]);
            __half2 b = __floats2half2_rn(v[4 * p + 2], v[4 * p + 3]);
            sts64(wb + p * 8, *(uint32_t*)&a, *(uint32_t*)&b);
        }
    }
}

// ---------------------------------------------------------------- main kernel
__global__ void __launch_bounds__(THREADS, OCC)
kan_mma_kernel(const float* __restrict__ x, float* __restrict__ out,
               int n_rows, int ntiles)
{
    extern __shared__ __align__(16) unsigned char smem[];
    const uint32_t sbase = smem_u32(smem);
    const int tid  = threadIdx.x;
    const int lane = tid & 31;
    const int wid  = tid >> 5;
    const int mw   = wid & 3;    // M warp: rows mw*32
    const int nw   = wid >> 2;   // N warp: cols nw*32

    const int lrow = lane & 15, lcol = lane >> 4;
    const uint32_t aOff = (uint32_t)(mw * 32 + lrow) * A_STRIDE_B + lcol * 16;

    int buf = 0;
    if (blockIdx.x < (unsigned)ntiles)
        gen_chunk(x, sbase, (long)blockIdx.x * TILE_M, n_rows, 0, 0, tid);
    __syncthreads();

    for (int tile = blockIdx.x; tile < ntiles; tile += gridDim.x) {
        const long tile_row0 = (long)tile * TILE_M;

        float d[2][4][4];
        #pragma unroll
        for (int mt = 0; mt < 2; mt++)
            #pragma unroll
            for (int j = 0; j < 4; j++)
                #pragma unroll
                for (int e = 0; e < 4; e++) d[mt][j][e] = 0.f;

        for (int ch = 0; ch < NCHUNK; ch++) {
            // produce next chunk (next tile's chunk 0 when wrapping)
            const int  ntile = (ch < NCHUNK - 1) ? tile : tile + gridDim.x;
            const int  nch   = (ch < NCHUNK - 1) ? ch + 1 : 0;
            if (ntile < ntiles)
                gen_chunk(x, sbase, (long)ntile * TILE_M, n_rows, nch, buf ^ 1, tid);

            // === mma on current buffer: 5 k-steps x (2 mt x 4 nt) ===
            const uint32_t aBase = sbase + buf * ABUF_BYTES + aOff;
            #pragma unroll
            for (int s = 0; s < KSTEPS; s++) {
                uint32_t aAddr = aBase + s * 32;
                uint32_t ah[2][4];
                ldm4(ah[0], aAddr);
                ldm4(ah[1], aAddr + 16 * A_STRIDE_B);

                uint32_t bh[4][2];
                const int fragIdx = ((ch * KSTEPS + s) * 8 + nw * 4);
                #pragma unroll
                for (int j = 0; j < 4; j++) {
                    uint2 vh = __ldg((const uint2*)(g_Bh + (fragIdx + j) * 256 + lane * 8));
                    bh[j][0] = vh.x; bh[j][1] = vh.y;
                }

                #pragma unroll
                for (int mt = 0; mt < 2; mt++)
                    #pragma unroll
                    for (int j = 0; j < 4; j++)
                        mma16816(d[mt][j], ah[mt], bh[j]);
            }
            __syncthreads();
            buf ^= 1;
        }

        // ---- epilogue: add fp32 constant (read straight from L1-hot g_c0), store ----
        #pragma unroll
        for (int mt = 0; mt < 2; mt++) {
            #pragma unroll
            for (int half = 0; half < 2; half++) {
                const long grow = tile_row0 + mw * 32 + mt * 16 + (lane >> 2) + half * 8;
                if (grow < n_rows) {
                    #pragma unroll
                    for (int j = 0; j < 4; j++) {
                        const int col = nw * 32 + j * 8 + (lane & 3) * 2;
                        float2 v;
                        v.x = d[mt][j][half * 2 + 0] + __ldg(&g_c0[col]);
                        v.y = d[mt][j][half * 2 + 1] + __ldg(&g_c0[col + 1]);
                        *(float2*)(out + grow * HID + col) = v;
                    }
                }
            }
        }
    }
}

// ---------------------------------------------------------------- launch
extern "C" void kernel_launch(void* const* d_in, const int* in_sizes, int n_in,
                              void* d_out, int out_size)
{
    const float* x = (const float*)d_in[0];
    const float* W = (const float*)d_in[1];
    const float* b = (const float*)d_in[2];
    float* out = (float*)d_out;

    const int n_rows = in_sizes[0] / IN_DIM;    // 131072
    const int ntiles = (n_rows + TILE_M - 1) / TILE_M;
    const int grid = ntiles < NCTAS ? ntiles : NCTAS;

    cudaFuncSetAttribute(kan_mma_kernel,
                         cudaFuncAttributeMaxDynamicSharedMemorySize, SMEM_TOTAL);

    prep_kernel<<<(KS_TOTAL * 8 * 32 + 255) / 256, 256>>>(W, b);
    kan_mma_kernel<<<grid, THREADS, SMEM_TOTAL>>>(x, out, n_rows, ntiles);
}

// round 13
// speedup vs baseline: 1.1863x; 1.1114x over previous
#include <cuda_runtime.h>
#include <cuda_bf16.h>
#include <cuda_fp16.h>
#include <cstdint>

#define IN_DIM   32
#define NB       11
#define FPAD     10                    // basis cols per feature in GEMM (sin/cos only)
#define HID      64
#define TILE_M   128
#define NCHUNK   2
#define FPC      16                    // features per chunk
#define KSTEPS   10                    // k16-steps per chunk (160 cols)
#define KS_TOTAL 20
#define THREADS  256
#define NCTAS    296                   // 148 SMs x 2 resident CTAs

#define A_STRIDE_B  336                // bytes per A row (168 halves; 160 used), 21*16

// ---- SMEM layout (bytes): double-buffered A (fp16) ----
#define ABUF_BYTES  (TILE_M * A_STRIDE_B)       // 43008
#define SMEM_TOTAL  (2 * ABUF_BYTES)            // 86016

#define BFRAG_BYTES (KS_TOTAL * 8 * 32 * 8)     // 40960

__device__ __align__(16) unsigned char g_Bh[BFRAG_BYTES];   // fp16 fragments
__device__ float g_c0[HID];            // sum_f (W[f][0][:] + b[f][:]), fp32 exact

// ---------------------------------------------------------------- helpers
__device__ __forceinline__ uint32_t smem_u32(const void* p) {
    uint32_t a;
    asm("{ .reg .u64 t; cvta.to.shared.u64 t, %1; cvt.u32.u64 %0, t; }"
        : "=r"(a) : "l"(p));
    return a;
}
__device__ __forceinline__ void ldm4(uint32_t* r, uint32_t a) {
    asm volatile("ldmatrix.sync.aligned.m8n8.x4.shared.b16 {%0,%1,%2,%3}, [%4];"
                 : "=r"(r[0]), "=r"(r[1]), "=r"(r[2]), "=r"(r[3]) : "r"(a));
}
__device__ __forceinline__ void sts64(uint32_t a, uint32_t v0, uint32_t v1) {
    asm volatile("st.shared.v2.b32 [%0], {%1, %2};" :: "r"(a), "r"(v0), "r"(v1) : "memory");
}
__device__ __forceinline__ void mma16816(float* d, const uint32_t* a, const uint32_t* b) {
    asm volatile(
        "mma.sync.aligned.m16n8k16.row.col.f32.f16.f16.f32 "
        "{%0,%1,%2,%3}, {%4,%5,%6,%7}, {%8,%9}, {%0,%1,%2,%3};"
        : "+f"(d[0]), "+f"(d[1]), "+f"(d[2]), "+f"(d[3])
        : "r"(a[0]), "r"(a[1]), "r"(a[2]), "r"(a[3]), "r"(b[0]), "r"(b[1]));
}

// sin/cos harmonics 1..5 of xv -> v[10] = {s1,c1,s2,c2,...,s5,c5}
// MUFU-based: 2x sin.approx/cos.approx (HW range reduction, abs err ~1e-6),
// then 4-deep product recurrence. Short dependency chain vs polynomial.
__device__ __forceinline__ void sincos_harm(float xv, float* v) {
    float s1, c1;
    __sincosf(xv, &s1, &c1);

    float s2 = 2.f * s1 * c1;
    float c2 = fmaf(c1, c1, -(s1 * s1));
    float s3 = s2 * c1 + c2 * s1;
    float c3 = c2 * c1 - s2 * s1;
    float s4 = s3 * c1 + c3 * s1;
    float c4 = c3 * c1 - s3 * s1;
    float s5 = s4 * c1 + c4 * s1;
    float c5 = c4 * c1 - s4 * s1;
    v[0] = s1; v[1] = c1; v[2] = s2; v[3] = c2; v[4] = s3;
    v[5] = c3; v[6] = s4; v[7] = c4; v[8] = s5; v[9] = c5;
}

// ---------------------------------------------------------------- prep kernel
// B[k][n], k = f*10 + c (c -> basis col c+1) as fp16 in mma B-fragment layout.
// Also g_c0 = sum_f(W[f][0]+b[f]).
__global__ void prep_kernel(const float* __restrict__ W, const float* __restrict__ bias) {
    int idx = blockIdx.x * blockDim.x + threadIdx.x;
    if (idx < HID) {
        float s = 0.f;
        #pragma unroll
        for (int f = 0; f < IN_DIM; f++)
            s += W[(f * NB) * HID + idx] + bias[f * HID + idx];
        g_c0[idx] = s;
    }
    if (idx >= KS_TOTAL * 8 * 32) return;
    int t   = idx & 31;
    int nt  = (idx >> 5) & 7;
    int ksg = idx >> 8;
    int n     = nt * 8 + (t >> 2);
    int kbase = ksg * 16 + (t & 3) * 2;

    uint32_t hi[2];
    #pragma unroll
    for (int half = 0; half < 2; half++) {
        int k0 = kbase + half * 8;
        float v0 = W[((k0 / FPAD) * NB + (k0 % FPAD) + 1) * HID + n];
        int k1 = k0 + 1;
        float v1 = W[((k1 / FPAD) * NB + (k1 % FPAD) + 1) * HID + n];
        __half2 h2 = __floats2half2_rn(v0, v1);
        hi[half] = *(uint32_t*)&h2;
    }
    *(uint2*)(g_Bh + idx * 8) = make_uint2(hi[0], hi[1]);
}

// ---------------------------------------------------------------- A generation
// 1024 jobs: 128 rows x 8 feature-pairs; each job does 2 sincos + 5 STS.64
__device__ __forceinline__ void gen_chunk(const float* __restrict__ x,
                                          uint32_t sbase, long row0, int n_rows,
                                          int ch, int buf, int tid)
{
    const uint32_t hoff = sbase + buf * ABUF_BYTES;
    #pragma unroll
    for (int i = 0; i < 4; i++) {
        const int job = tid + THREADS * i;     // 0..1023
        const int r   = job >> 3;
        const int fp  = job & 7;
        const long grow = row0 + r;
        const int f0 = ch * FPC + fp * 2;

        float2 xv2 = make_float2(0.f, 0.f);
        if (grow < n_rows)
            xv2 = __ldg((const float2*)(x + grow * IN_DIM + f0));

        float v[20];
        sincos_harm(xv2.x, v);
        sincos_harm(xv2.y, v + 10);

        const uint32_t wb = hoff + r * A_STRIDE_B + fp * 40;
        #pragma unroll
        for (int p = 0; p < 5; p++) {
            __half2 a = __floats2half2_rn(v[4 * p + 0], v[4 * p + 1]);
            __half2 b = __floats2half2_rn(v[4 * p + 2], v[4 * p + 3]);
            sts64(wb + p * 8, *(uint32_t*)&a, *(uint32_t*)&b);
        }
    }
}

// ---------------------------------------------------------------- main kernel
__global__ void __launch_bounds__(THREADS, 2)
kan_mma_kernel(const float* __restrict__ x, float* __restrict__ out,
               int n_rows, int ntiles)
{
    extern __shared__ __align__(16) unsigned char smem[];
    const uint32_t sbase = smem_u32(smem);
    const int tid  = threadIdx.x;
    const int lane = tid & 31;
    const int wid  = tid >> 5;
    const int mw   = wid & 3;    // M warp: rows mw*32
    const int nw   = wid >> 2;   // N warp: cols nw*32

    const int lrow = lane & 15, lcol = lane >> 4;
    const uint32_t aOff = (uint32_t)(mw * 32 + lrow) * A_STRIDE_B + lcol * 16;

    // epilogue constant (ones-col + bias), fp32 exact
    float c0v[4][2];
    #pragma unroll
    for (int j = 0; j < 4; j++) {
        const int col = nw * 32 + j * 8 + (lane & 3) * 2;
        c0v[j][0] = __ldg(&g_c0[col]);
        c0v[j][1] = __ldg(&g_c0[col + 1]);
    }

    int buf = 0;
    if (blockIdx.x < (unsigned)ntiles)
        gen_chunk(x, sbase, (long)blockIdx.x * TILE_M, n_rows, 0, 0, tid);
    __syncthreads();

    for (int tile = blockIdx.x; tile < ntiles; tile += gridDim.x) {
        const long tile_row0 = (long)tile * TILE_M;

        float d[2][4][4];
        #pragma unroll
        for (int mt = 0; mt < 2; mt++)
            #pragma unroll
            for (int j = 0; j < 4; j++)
                #pragma unroll
                for (int e = 0; e < 4; e++) d[mt][j][e] = 0.f;

        for (int ch = 0; ch < NCHUNK; ch++) {
            // produce next chunk (next tile's chunk 0 when wrapping)
            const int  ntile = (ch < NCHUNK - 1) ? tile : tile + gridDim.x;
            const int  nch   = (ch < NCHUNK - 1) ? ch + 1 : 0;
            if (ntile < ntiles)
                gen_chunk(x, sbase, (long)ntile * TILE_M, n_rows, nch, buf ^ 1, tid);

            // === mma on current buffer: 10 k-steps x (2 mt x 4 nt) ===
            const uint32_t aBase = sbase + buf * ABUF_BYTES + aOff;
            #pragma unroll
            for (int s = 0; s < KSTEPS; s++) {
                uint32_t aAddr = aBase + s * 32;
                uint32_t ah[2][4];
                ldm4(ah[0], aAddr);
                ldm4(ah[1], aAddr + 16 * A_STRIDE_B);

                uint32_t bh[4][2];
                const int fragIdx = ((ch * KSTEPS + s) * 8 + nw * 4);
                #pragma unroll
                for (int j = 0; j < 4; j++) {
                    uint2 vh = __ldg((const uint2*)(g_Bh + (fragIdx + j) * 256 + lane * 8));
                    bh[j][0] = vh.x; bh[j][1] = vh.y;
                }

                #pragma unroll
                for (int mt = 0; mt < 2; mt++)
                    #pragma unroll
                    for (int j = 0; j < 4; j++)
                        mma16816(d[mt][j], ah[mt], bh[j]);
            }
            __syncthreads();
            buf ^= 1;
        }

        // ---- epilogue: add fp32 constant, store ----
        #pragma unroll
        for (int mt = 0; mt < 2; mt++) {
            #pragma unroll
            for (int half = 0; half < 2; half++) {
                const long grow = tile_row0 + mw * 32 + mt * 16 + (lane >> 2) + half * 8;
                if (grow < n_rows) {
                    #pragma unroll
                    for (int j = 0; j < 4; j++) {
                        const int col = nw * 32 + j * 8 + (lane & 3) * 2;
                        float2 v;
                        v.x = d[mt][j][half * 2 + 0] + c0v[j][0];
                        v.y = d[mt][j][half * 2 + 1] + c0v[j][1];
                        *(float2*)(out + grow * HID + col) = v;
                    }
                }
            }
        }
    }
}

// ---------------------------------------------------------------- launch
extern "C" void kernel_launch(void* const* d_in, const int* in_sizes, int n_in,
                              void* d_out, int out_size)
{
    const float* x = (const float*)d_in[0];
    const float* W = (const float*)d_in[1];
    const float* b = (const float*)d_in[2];
    float* out = (float*)d_out;

    const int n_rows = in_sizes[0] / IN_DIM;    // 131072
    const int ntiles = (n_rows + TILE_M - 1) / TILE_M;
    const int grid = ntiles < NCTAS ? ntiles : NCTAS;

    cudaFuncSetAttribute(kan_mma_kernel,
                         cudaFuncAttributeMaxDynamicSharedMemorySize, SMEM_TOTAL);

    prep_kernel<<<(KS_TOTAL * 8 * 32 + 255) / 256, 256>>>(W, b);
    kan_mma_kernel<<<grid, THREADS, SMEM_TOTAL>>>(x, out, n_rows, ntiles);
}